// round 10
// baseline (speedup 1.0000x reference)
#include <cuda_runtime.h>
#include <cuda_fp16.h>
#include <cstdint>

// Problem constants
constexpr int N_ROWS = 32768;          // 8*4096
constexpr int D      = 512;
constexpr int KSZ    = 4096;

// Output layout (float32), reference tuple order
constexpr size_t OFF_F    = 0;
constexpr size_t OFF_LOSS = (size_t)N_ROWS * D;
constexpr size_t OFF_K    = OFF_LOSS + 1;
constexpr size_t OFF_ECS  = OFF_K + (size_t)KSZ * D;
constexpr size_t OFF_EMAW = OFF_ECS + KSZ;

// ---------------- device scratch ----------------
__device__ __align__(16) __half g_fhi[(size_t)N_ROWS * D];
__device__ __align__(16) __half g_flo[(size_t)N_ROWS * D];
__device__ __align__(16) __half g_khi[(size_t)KSZ * D];
__device__ __align__(16) __half g_klo[(size_t)KSZ * D];
__device__ float               g_y2[KSZ];
__device__ unsigned long long  g_best[N_ROWS];
__device__ float               g_counts[KSZ];
__device__ float               g_dw[(size_t)KSZ * D];
__device__ double              g_loss;
__device__ double              g_n;

// ---------------- helpers ----------------
__device__ __forceinline__ uint32_t smem_u32(const void* p) {
    uint32_t a;
    asm("{ .reg .u64 t; cvta.to.shared.u64 t, %1; cvt.u32.u64 %0, t; }" : "=r"(a) : "l"(p));
    return a;
}
__device__ __forceinline__ void cp16(uint32_t s, const void* g) {
    asm volatile("cp.async.cg.shared.global [%0], [%1], 16;" :: "r"(s), "l"(g));
}
__device__ __forceinline__ unsigned int fkey(float v) {
    unsigned int b = __float_as_uint(v);
    return (b & 0x80000000u) ? ~b : (b | 0x80000000u);
}
// m16n8k16 fp16 MMA, fp32 accumulate (baseline PTX, tensor pipe)
__device__ __forceinline__ void mma16(float* d, const uint32_t* a, const uint32_t* b) {
    asm volatile("mma.sync.aligned.m16n8k16.row.col.f32.f16.f16.f32 "
                 "{%0,%1,%2,%3}, {%4,%5,%6,%7}, {%8,%9}, {%0,%1,%2,%3};"
                 : "+f"(d[0]), "+f"(d[1]), "+f"(d[2]), "+f"(d[3])
                 : "r"(a[0]), "r"(a[1]), "r"(a[2]), "r"(a[3]), "r"(b[0]), "r"(b[1]));
}
// ldmatrix x4: four 8x8 b16 matrices, per-lane addresses
__device__ __forceinline__ void ldsm4(uint32_t& r0, uint32_t& r1, uint32_t& r2,
                                      uint32_t& r3, uint32_t addr) {
    asm volatile("ldmatrix.sync.aligned.m8n8.x4.shared.b16 {%0,%1,%2,%3}, [%4];"
                 : "=r"(r0), "=r"(r1), "=r"(r2), "=r"(r3) : "r"(addr));
}

// ---------------- kernel 0: zero scratch ----------------
__global__ void zero_kernel() {
    int i = blockIdx.x * blockDim.x + threadIdx.x;   // covers KSZ*D
    g_dw[i] = 0.0f;
    if (i < KSZ)    g_counts[i] = 0.0f;
    if (i < N_ROWS) g_best[i] = ~0ULL;
    if (i == 0) { g_loss = 0.0; g_n = 0.0; }
}

// ---------------- kernel 1: fp16 hi/lo split ----------------
__global__ void split_kernel(const float* __restrict__ f, const float* __restrict__ Kc) {
    size_t i = (size_t)blockIdx.x * 256 + threadIdx.x;   // covers N_ROWS*D
    float x = f[i];
    __half h = __float2half_rn(x);
    g_fhi[i] = h;
    g_flo[i] = __float2half_rn(x - __half2float(h));
    if (i < (size_t)KSZ * D) {
        float y = Kc[i];
        __half hy = __float2half_rn(y);
        g_khi[i] = hy;
        g_klo[i] = __float2half_rn(y - __half2float(hy));
    }
}

// ---------------- kernel 2: code norms (fp32 exact) ----------------
__global__ void y2_kernel(const float* __restrict__ Kc) {
    int k = blockIdx.x;
    const float4* kv = (const float4*)(Kc + (size_t)k * D);
    float4 v = kv[threadIdx.x];
    float s = v.x * v.x + v.y * v.y + v.z * v.z + v.w * v.w;
    #pragma unroll
    for (int o = 16; o > 0; o >>= 1) s += __shfl_down_sync(0xffffffffu, s, o);
    __shared__ float sh[4];
    if ((threadIdx.x & 31) == 0) sh[threadIdx.x >> 5] = s;
    __syncthreads();
    if (threadIdx.x == 0) g_y2[k] = sh[0] + sh[1] + sh[2] + sh[3];
}

// ---------------- kernel 3: 3xFP16 mma.sync GEMM + argmin epilogue ----------------
// CTA tile 256 rows x 128 codes; 8 warps (4m x 2n) of 64x64; KBLK=32 halves; 3 stages.
// Fragment loads via ldmatrix.x4 (4x fewer shared-load issues than LDS.32 path).
constexpr int KBLK   = 32;             // halves per k-block
constexpr int NKB    = D / KBLK;       // 16
constexpr int STAGES = 3;
constexpr int CODT   = KSZ / 128;      // 32 code tiles (inner for L2 reuse)

// smem stage layout in halves (row stride 40 halves = 20 words: conflict-free
// for both cp.async stores and ldmatrix row fetches)
constexpr int AH_H = 0;                // A hi: 256 x 40
constexpr int AL_H = 10240;            // A lo
constexpr int BH_H = 20480;            // B hi: 128 x 40
constexpr int BL_H = 25600;            // B lo
constexpr int STG_H = 30720;           // halves per stage
constexpr uint32_t STG_B = STG_H * 2;  // 61440 B
constexpr uint32_t SMEM_DYN = STAGES * STG_B;  // 184320 B

__global__ void __launch_bounds__(256, 1)
gemm_kernel() {
    extern __shared__ __half smem[];
    __shared__ unsigned long long best[256];
    __shared__ float sy2[128];

    const uint32_t sbase = smem_u32(smem);
    const int tid = threadIdx.x;
    const int wid = tid >> 5;
    const int lane = tid & 31;
    const int g = lane >> 2;        // groupID
    const int c = lane & 3;         // threadInGroup
    const int wm = wid >> 1;        // 0..3 -> warp rows wm*64
    const int wn = wid & 1;         // 0..1 -> warp cols wn*64
    const int wr = wm * 64;
    const int wc = wn * 64;

    const int codetile = blockIdx.x & (CODT - 1);
    const int rowtile  = blockIdx.x >> 5;
    const int row0  = rowtile * 256;
    const int code0 = codetile * 128;

    best[tid] = ~0ULL;
    if (tid < 128) sy2[tid] = g_y2[code0 + tid];

    const __half* fa_hi = g_fhi + (size_t)row0 * D;
    const __half* fa_lo = g_flo + (size_t)row0 * D;
    const __half* kb_hi = g_khi + (size_t)code0 * D;
    const __half* kb_lo = g_klo + (size_t)code0 * D;

    // stage fill: 12 cp.async(16B) per thread
    auto fill = [&](int kb) {
        const uint32_t sb = sbase + (uint32_t)(kb % STAGES) * STG_B;
        const int koff = kb * KBLK;
        #pragma unroll
        for (int rep = 0; rep < 4; rep++) {           // A: 1024 chunks per split
            const int idx = tid + rep * 256;
            const int r = idx >> 2, kc = idx & 3;
            const uint32_t d = (uint32_t)(r * 80 + kc * 16);
            const size_t gsrc = (size_t)r * D + koff + kc * 8;
            cp16(sb + AH_H * 2 + d, fa_hi + gsrc);
            cp16(sb + AL_H * 2 + d, fa_lo + gsrc);
        }
        #pragma unroll
        for (int rep = 0; rep < 2; rep++) {           // B: 512 chunks per split
            const int idx = tid + rep * 256;
            const int r = idx >> 2, kc = idx & 3;
            const uint32_t d = (uint32_t)(r * 80 + kc * 16);
            const size_t gsrc = (size_t)r * D + koff + kc * 8;
            cp16(sb + BH_H * 2 + d, kb_hi + gsrc);
            cp16(sb + BL_H * 2 + d, kb_lo + gsrc);
        }
        asm volatile("cp.async.commit_group;" ::: "memory");
    };

    fill(0);
    fill(1);

    float acc[4][8][4];
    #pragma unroll
    for (int mt = 0; mt < 4; mt++)
        #pragma unroll
        for (int nt = 0; nt < 8; nt++)
            #pragma unroll
            for (int k = 0; k < 4; k++) acc[mt][nt][k] = 0.0f;

    // per-lane ldmatrix address components (constant across kb)
    // A x4: matrices {rows 0-7,k0}, {rows 8-15,k0}, {rows 0-7,k0+8}, {rows 8-15,k0+8}
    const int a_row = wr + (lane & 15);          // + mt*16
    const int a_kk  = (lane >> 4) * 8;           // + k0
    // B x4 over an nt-pair: {nt0,k0},{nt0,k0+8},{nt1,k0},{nt1,k0+8}
    const int b_m   = lane >> 3;                 // 0..3
    const int b_row = wc + ((b_m >> 1) * 8) + (lane & 7);  // + pair*16
    const int b_kk  = (b_m & 1) * 8;             // + k0

    for (int kb = 0; kb < NKB; kb++) {
        asm volatile("cp.async.wait_group 1;" ::: "memory");
        __syncthreads();
        if (kb + 2 < NKB) fill(kb + 2);
        else asm volatile("cp.async.commit_group;" ::: "memory");

        const uint32_t Sst = sbase + (uint32_t)(kb % STAGES) * STG_B;

        #pragma unroll
        for (int ks = 0; ks < 2; ks++) {
            const int k0 = ks * 16;
            // base addresses for this k-step (bytes)
            const uint32_t aBase = Sst + (uint32_t)((AH_H + a_row * 40 + a_kk + k0) * 2);
            const uint32_t bBase = Sst + (uint32_t)((BH_H + b_row * 40 + b_kk + k0) * 2);

            uint32_t bh[8][2], bl[8][2];
            #pragma unroll
            for (int pr = 0; pr < 4; pr++) {     // nt pair -> nt=2*pr, 2*pr+1
                const uint32_t ba = bBase + (uint32_t)(pr * 16 * 80);   // 16 rows * 80B
                ldsm4(bh[2*pr][0], bh[2*pr][1], bh[2*pr+1][0], bh[2*pr+1][1], ba);
                ldsm4(bl[2*pr][0], bl[2*pr][1], bl[2*pr+1][0], bl[2*pr+1][1],
                      ba + (uint32_t)((BL_H - BH_H) * 2));
            }
            uint32_t ah[4][4], al[4][4];
            #pragma unroll
            for (int mt = 0; mt < 4; mt++) {
                const uint32_t aa = aBase + (uint32_t)(mt * 16 * 80);   // 16 rows * 80B
                ldsm4(ah[mt][0], ah[mt][1], ah[mt][2], ah[mt][3], aa);
                ldsm4(al[mt][0], al[mt][1], al[mt][2], al[mt][3],
                      aa + (uint32_t)((AL_H - AH_H) * 2));
            }
            // term-major issue: independent accumulators between reuses
            #pragma unroll
            for (int mt = 0; mt < 4; mt++)
                #pragma unroll
                for (int nt = 0; nt < 8; nt++)
                    mma16(acc[mt][nt], ah[mt], bh[nt]);   // hi*hi
            #pragma unroll
            for (int mt = 0; mt < 4; mt++)
                #pragma unroll
                for (int nt = 0; nt < 8; nt++)
                    mma16(acc[mt][nt], ah[mt], bl[nt]);   // hi*lo
            #pragma unroll
            for (int mt = 0; mt < 4; mt++)
                #pragma unroll
                for (int nt = 0; nt < 8; nt++)
                    mma16(acc[mt][nt], al[mt], bh[nt]);   // lo*hi
        }
        __syncthreads();
    }

    // epilogue: per-row argmin over this CTA's 128 codes
    #pragma unroll
    for (int mt = 0; mt < 4; mt++) {
        #pragma unroll
        for (int half = 0; half < 2; half++) {
            const int r = wr + mt * 16 + g + half * 8;   // local row
            float bv = 3.4e38f; int bj = 0;
            #pragma unroll
            for (int nt = 0; nt < 8; nt++) {
                #pragma unroll
                for (int j = 0; j < 2; j++) {
                    const int col = wc + nt * 8 + c * 2 + j;
                    const float sc = sy2[col] - 2.0f * acc[mt][nt][half * 2 + j];
                    if (sc < bv) { bv = sc; bj = col; }
                }
            }
            const unsigned long long pk =
                ((unsigned long long)fkey(bv) << 32) | (unsigned)(code0 + bj);
            atomicMin(&best[r], pk);
        }
    }
    __syncthreads();
    atomicMin(&g_best[row0 + tid], best[tid]);
}

// ---------------- kernel 4: gather + loss + EMA scatter ----------------
__global__ void gather_kernel(const float* __restrict__ f, const float* __restrict__ Kc,
                              float* __restrict__ out) {
    const int row = blockIdx.x * 2 + (threadIdx.x >> 7);
    const int c4  = threadIdx.x & 127;
    const int idx = (int)(unsigned)(g_best[row] & 0xFFFFFFFFULL);
    float4 kv = __ldg((const float4*)(Kc + (size_t)idx * D) + c4);
    float4 fv = __ldg((const float4*)(f + (size_t)row * D) + c4);
    ((float4*)(out + OFF_F))[(size_t)row * (D / 4) + c4] = kv;
    float dx = kv.x - fv.x, dy = kv.y - fv.y, dz = kv.z - fv.z, dw_ = kv.w - fv.w;
    float s = dx * dx + dy * dy + dz * dz + dw_ * dw_;
    float* dwp = g_dw + (size_t)idx * D + c4 * 4;
    atomicAdd(dwp + 0, fv.x);
    atomicAdd(dwp + 1, fv.y);
    atomicAdd(dwp + 2, fv.z);
    atomicAdd(dwp + 3, fv.w);
    if (c4 == 0) atomicAdd(&g_counts[idx], 1.0f);
    #pragma unroll
    for (int o = 16; o > 0; o >>= 1) s += __shfl_down_sync(0xffffffffu, s, o);
    __shared__ float sh[8];
    if ((threadIdx.x & 31) == 0) sh[threadIdx.x >> 5] = s;
    __syncthreads();
    if (threadIdx.x == 0) {
        float tot = 0.0f;
        #pragma unroll
        for (int w = 0; w < 8; w++) tot += sh[w];
        atomicAdd(&g_loss, (double)tot);
    }
}

// ---------------- kernel 5: new_ecs + n ----------------
__global__ void ecs_kernel(const float* __restrict__ ecs, float* __restrict__ out) {
    const int i = blockIdx.x * 256 + threadIdx.x;
    float newc = ecs[i] * 0.99f + 0.01f * g_counts[i];
    out[OFF_ECS + i] = newc;
    float s = newc;
    #pragma unroll
    for (int o = 16; o > 0; o >>= 1) s += __shfl_down_sync(0xffffffffu, s, o);
    __shared__ float sh[8];
    if ((threadIdx.x & 31) == 0) sh[threadIdx.x >> 5] = s;
    __syncthreads();
    if (threadIdx.x == 0) {
        float tot = 0.0f;
        #pragma unroll
        for (int w = 0; w < 8; w++) tot += sh[w];
        atomicAdd(&g_n, (double)tot);
    }
}

// ---------------- kernel 6: new_ema_w, new_K, loss ----------------
__global__ void final_kernel(const float* __restrict__ emaw, float* __restrict__ out) {
    const size_t i = (size_t)blockIdx.x * 256 + threadIdx.x;
    const int k = (int)(i >> 9);   // D = 512
    float neww = emaw[i] * 0.99f + 0.01f * g_dw[i];
    out[OFF_EMAW + i] = neww;
    float nn = (float)g_n;
    float newc = out[OFF_ECS + k];
    float smoothed = (newc + 1e-5f) / (nn + 4096.0f * 1e-5f) * nn;
    out[OFF_K + i] = neww / smoothed;
    if (i == 0)
        out[OFF_LOSS] = (float)(g_loss / ((double)N_ROWS * (double)D));
}

extern "C" void kernel_launch(void* const* d_in, const int* in_sizes, int n_in,
                              void* d_out, int out_size) {
    const float* f    = (const float*)d_in[0];  // [8,4096,512]
    const float* Kc   = (const float*)d_in[1];  // [4096,512]
    const float* ecs  = (const float*)d_in[2];  // [4096]
    const float* emaw = (const float*)d_in[3];  // [4096,512]
    float* out = (float*)d_out;

    cudaFuncSetAttribute(gemm_kernel, cudaFuncAttributeMaxDynamicSharedMemorySize, SMEM_DYN);

    zero_kernel<<<(KSZ * D) / 256, 256>>>();
    split_kernel<<<(N_ROWS * D) / 256, 256>>>(f, Kc);
    y2_kernel<<<KSZ, 128>>>(Kc);
    gemm_kernel<<<(N_ROWS / 256) * CODT, 256, SMEM_DYN>>>();
    gather_kernel<<<N_ROWS / 2, 256>>>(f, Kc, out);
    ecs_kernel<<<KSZ / 256, 256>>>(ecs, out);
    final_kernel<<<(KSZ * D) / 256, 256>>>(emaw, out);
}

// round 11
// speedup vs baseline: 2.3783x; 2.3783x over previous
#include <cuda_runtime.h>
#include <cuda_fp16.h>
#include <cstdint>

// Problem constants
constexpr int N_ROWS = 32768;          // 8*4096
constexpr int D      = 512;
constexpr int KSZ    = 4096;

// Output layout (float32), reference tuple order
constexpr size_t OFF_F    = 0;
constexpr size_t OFF_LOSS = (size_t)N_ROWS * D;
constexpr size_t OFF_K    = OFF_LOSS + 1;
constexpr size_t OFF_ECS  = OFF_K + (size_t)KSZ * D;
constexpr size_t OFF_EMAW = OFF_ECS + KSZ;

// ---------------- device scratch ----------------
__device__ __align__(16) __half g_fh[(size_t)N_ROWS * D];
__device__ __align__(16) __half g_kh[(size_t)KSZ * D];
__device__ __align__(16) __half g_scores[(size_t)N_ROWS * KSZ];   // 256MB approx scores
__device__ float               g_y2[KSZ];
__device__ int                 g_idx[N_ROWS];
__device__ float               g_counts[KSZ];
__device__ float               g_dw[(size_t)KSZ * D];
__device__ double              g_loss;
__device__ double              g_n;

// ---------------- helpers ----------------
__device__ __forceinline__ uint32_t smem_u32(const void* p) {
    uint32_t a;
    asm("{ .reg .u64 t; cvta.to.shared.u64 t, %1; cvt.u32.u64 %0, t; }" : "=r"(a) : "l"(p));
    return a;
}
__device__ __forceinline__ void cp16(uint32_t s, const void* g) {
    asm volatile("cp.async.cg.shared.global [%0], [%1], 16;" :: "r"(s), "l"(g));
}
__device__ __forceinline__ unsigned int fkey(float v) {
    unsigned int b = __float_as_uint(v);
    return (b & 0x80000000u) ? ~b : (b | 0x80000000u);
}
// m16n8k16 fp16 MMA, fp32 accumulate (baseline PTX, tensor pipe)
__device__ __forceinline__ void mma16(float* d, const uint32_t* a, const uint32_t* b) {
    asm volatile("mma.sync.aligned.m16n8k16.row.col.f32.f16.f16.f32 "
                 "{%0,%1,%2,%3}, {%4,%5,%6,%7}, {%8,%9}, {%0,%1,%2,%3};"
                 : "+f"(d[0]), "+f"(d[1]), "+f"(d[2]), "+f"(d[3])
                 : "r"(a[0]), "r"(a[1]), "r"(a[2]), "r"(a[3]), "r"(b[0]), "r"(b[1]));
}

// ---------------- kernel 0: zero scratch ----------------
__global__ void zero_kernel() {
    int i = blockIdx.x * blockDim.x + threadIdx.x;   // covers KSZ*D
    g_dw[i] = 0.0f;
    if (i < KSZ) g_counts[i] = 0.0f;
    if (i == 0) { g_loss = 0.0; g_n = 0.0; }
}

// ---------------- kernel 1: fp16 downcast ----------------
__global__ void split_kernel(const float* __restrict__ f, const float* __restrict__ Kc) {
    size_t i = (size_t)blockIdx.x * 256 + threadIdx.x;   // covers N_ROWS*D
    g_fh[i] = __float2half_rn(f[i]);
    if (i < (size_t)KSZ * D) g_kh[i] = __float2half_rn(Kc[i]);
}

// ---------------- kernel 2: code norms (fp32 exact) ----------------
__global__ void y2_kernel(const float* __restrict__ Kc) {
    int k = blockIdx.x;
    const float4* kv = (const float4*)(Kc + (size_t)k * D);
    float4 v = kv[threadIdx.x];
    float s = v.x * v.x + v.y * v.y + v.z * v.z + v.w * v.w;
    #pragma unroll
    for (int o = 16; o > 0; o >>= 1) s += __shfl_down_sync(0xffffffffu, s, o);
    __shared__ float sh[4];
    if ((threadIdx.x & 31) == 0) sh[threadIdx.x >> 5] = s;
    __syncthreads();
    if (threadIdx.x == 0) g_y2[k] = sh[0] + sh[1] + sh[2] + sh[3];
}

// ---------------- kernel 3: 1-term fp16 GEMM, write approx scores ----------------
// CTA tile 256 rows x 128 codes; 8 warps (4m x 2n) of 64x64; KBLK=32 halves; 3 stages.
constexpr int KBLK   = 32;             // halves per k-block
constexpr int NKB    = D / KBLK;       // 16
constexpr int STAGES = 3;
constexpr int CODT   = KSZ / 128;      // 32 code tiles (inner for L2 reuse)

// smem stage layout in halves (row stride 40 halves = 20 words: conflict-free)
constexpr int AH_H = 0;                // A hi: 256 x 40
constexpr int BH_H = 10240;            // B hi: 128 x 40
constexpr int STG_H = 15360;           // halves per stage
constexpr uint32_t STG_B = STG_H * 2;  // 30720 B
constexpr uint32_t SMEM_DYN = STAGES * STG_B;  // 92160 B

__global__ void __launch_bounds__(256, 1)
gemm_kernel() {
    extern __shared__ __half smem[];
    __shared__ float sy2[128];

    const uint32_t sbase = smem_u32(smem);
    const int tid = threadIdx.x;
    const int wid = tid >> 5;
    const int lane = tid & 31;
    const int g = lane >> 2;        // groupID
    const int c = lane & 3;         // threadInGroup
    const int wm = wid >> 1;        // 0..3 -> warp rows wm*64
    const int wn = wid & 1;         // 0..1 -> warp cols wn*64
    const int wr = wm * 64;
    const int wc = wn * 64;

    const int codetile = blockIdx.x & (CODT - 1);
    const int rowtile  = blockIdx.x >> 5;
    const int row0  = rowtile * 256;
    const int code0 = codetile * 128;

    if (tid < 128) sy2[tid] = g_y2[code0 + tid];

    const __half* fa = g_fh + (size_t)row0 * D;
    const __half* kb_ = g_kh + (size_t)code0 * D;

    // stage fill: 6 cp.async(16B) per thread (A:4, B:2)
    auto fill = [&](int kb) {
        const uint32_t sb = sbase + (uint32_t)(kb % STAGES) * STG_B;
        const int koff = kb * KBLK;
        #pragma unroll
        for (int rep = 0; rep < 4; rep++) {           // A: 1024 chunks
            const int idx = tid + rep * 256;
            const int r = idx >> 2, kc = idx & 3;
            cp16(sb + AH_H * 2 + (uint32_t)(r * 80 + kc * 16),
                 fa + (size_t)r * D + koff + kc * 8);
        }
        #pragma unroll
        for (int rep = 0; rep < 2; rep++) {           // B: 512 chunks
            const int idx = tid + rep * 256;
            const int r = idx >> 2, kc = idx & 3;
            cp16(sb + BH_H * 2 + (uint32_t)(r * 80 + kc * 16),
                 kb_ + (size_t)r * D + koff + kc * 8);
        }
        asm volatile("cp.async.commit_group;" ::: "memory");
    };

    fill(0);
    fill(1);

    float acc[4][8][4];
    #pragma unroll
    for (int mt = 0; mt < 4; mt++)
        #pragma unroll
        for (int nt = 0; nt < 8; nt++)
            #pragma unroll
            for (int k = 0; k < 4; k++) acc[mt][nt][k] = 0.0f;

    for (int kb = 0; kb < NKB; kb++) {
        asm volatile("cp.async.wait_group 1;" ::: "memory");
        __syncthreads();
        // fill writes stage (kb+2)%3 == (kb-1)%3; its reads finished before
        // the sync above, so one sync per kb suffices.
        if (kb + 2 < NKB) fill(kb + 2);
        else asm volatile("cp.async.commit_group;" ::: "memory");

        const __half* S = smem + (size_t)(kb % STAGES) * STG_H;
        const __half* Sah = S + AH_H;
        const __half* Sbh = S + BH_H;

        #pragma unroll
        for (int ks = 0; ks < 2; ks++) {
            const int k0 = ks * 16;
            uint32_t bh[8][2];
            #pragma unroll
            for (int nt = 0; nt < 8; nt++) {
                const int n = wc + nt * 8 + g;
                bh[nt][0] = *(const uint32_t*)&Sbh[n * 40 + k0 + 2 * c];
                bh[nt][1] = *(const uint32_t*)&Sbh[n * 40 + k0 + 2 * c + 8];
            }
            uint32_t ah[4][4];
            #pragma unroll
            for (int mt = 0; mt < 4; mt++) {
                const int r = wr + mt * 16 + g;
                ah[mt][0] = *(const uint32_t*)&Sah[r * 40 + k0 + 2 * c];
                ah[mt][1] = *(const uint32_t*)&Sah[(r + 8) * 40 + k0 + 2 * c];
                ah[mt][2] = *(const uint32_t*)&Sah[r * 40 + k0 + 2 * c + 8];
                ah[mt][3] = *(const uint32_t*)&Sah[(r + 8) * 40 + k0 + 2 * c + 8];
            }
            #pragma unroll
            for (int mt = 0; mt < 4; mt++)
                #pragma unroll
                for (int nt = 0; nt < 8; nt++)
                    mma16(acc[mt][nt], ah[mt], bh[nt]);
        }
    }

    // epilogue: write approx scores (fp16) for this 256x128 tile
    #pragma unroll
    for (int mt = 0; mt < 4; mt++) {
        #pragma unroll
        for (int half = 0; half < 2; half++) {
            const int r = row0 + wr + mt * 16 + g + half * 8;
            __half* dst = g_scores + (size_t)r * KSZ + code0;
            #pragma unroll
            for (int nt = 0; nt < 8; nt++) {
                const int col = wc + nt * 8 + c * 2;
                float s0 = sy2[col]     - 2.0f * acc[mt][nt][half * 2 + 0];
                float s1 = sy2[col + 1] - 2.0f * acc[mt][nt][half * 2 + 1];
                *(__half2*)(dst + col) = __floats2half2_rn(s0, s1);
            }
        }
    }
}

// ---------------- kernel 4: exact argmin via candidate rescore ----------------
// One warp per row: scan 4096 fp16 scores, rescore all within MARGIN of the
// min exactly in fp32, pick packed-key min (ties -> lowest index).
constexpr float MARGIN = 6.0f;   // >> hard error bound (~0.9) of pass-1 scores

__global__ void __launch_bounds__(256, 4)
argmin_kernel(const float* __restrict__ f, const float* __restrict__ Kc) {
    const int w = threadIdx.x >> 5, lane = threadIdx.x & 31;
    const int row = blockIdx.x * 8 + w;
    const uint4* src = (const uint4*)(g_scores + (size_t)row * KSZ + lane * 128);

    // pass A: warp min of approx scores
    float m = 3.4e38f;
    #pragma unroll
    for (int it = 0; it < 16; it++) {
        uint4 v = src[it];
        const uint32_t vv[4] = {v.x, v.y, v.z, v.w};
        #pragma unroll
        for (int q = 0; q < 4; q++) {
            __half2 p = *(const __half2*)&vv[q];
            m = fminf(m, fminf(__low2float(p), __high2float(p)));
        }
    }
    #pragma unroll
    for (int o = 16; o > 0; o >>= 1)
        m = fminf(m, __shfl_xor_sync(0xffffffffu, m, o));
    const float thr = m + MARGIN;

    // pass B: enumerate candidates <= thr, exact fp32 rescore
    const float4* f4 = (const float4*)(f + (size_t)row * D);
    unsigned long long bestk = ~0ULL;
    for (int it = 0; it < 16; it++) {
        uint4 v = src[it];
        const uint32_t vv[4] = {v.x, v.y, v.z, v.w};
        int mask8 = 0;
        #pragma unroll
        for (int q = 0; q < 4; q++) {
            __half2 p = *(const __half2*)&vv[q];
            if (__low2float(p)  <= thr) mask8 |= 1 << (2 * q);
            if (__high2float(p) <= thr) mask8 |= 2 << (2 * q);
        }
        unsigned bal = __ballot_sync(0xffffffffu, mask8 != 0);
        while (bal) {
            const int s = __ffs(bal) - 1; bal &= bal - 1;
            int m8 = __shfl_sync(0xffffffffu, mask8, s);
            while (m8) {
                const int b = __ffs(m8) - 1; m8 &= m8 - 1;
                const int cand = s * 128 + it * 8 + b;
                // warp-cooperative exact fp32 dot
                const float4* k4 = (const float4*)(Kc + (size_t)cand * D);
                float ds = 0.0f;
                #pragma unroll
                for (int q = 0; q < 4; q++) {
                    float4 a = f4[q * 32 + lane];
                    float4 kk = k4[q * 32 + lane];
                    ds += a.x * kk.x + a.y * kk.y + a.z * kk.z + a.w * kk.w;
                }
                #pragma unroll
                for (int o = 16; o > 0; o >>= 1)
                    ds += __shfl_xor_sync(0xffffffffu, ds, o);
                const float sc = g_y2[cand] - 2.0f * ds;
                const unsigned long long key =
                    ((unsigned long long)fkey(sc) << 32) | (unsigned)cand;
                bestk = (key < bestk) ? key : bestk;
            }
        }
    }
    if (lane == 0) g_idx[row] = (int)(bestk & 0xFFFFFFFFULL);
}

// ---------------- kernel 5: gather + loss + EMA scatter ----------------
__global__ void gather_kernel(const float* __restrict__ f, const float* __restrict__ Kc,
                              float* __restrict__ out) {
    const int row = blockIdx.x * 2 + (threadIdx.x >> 7);
    const int c4  = threadIdx.x & 127;
    const int idx = g_idx[row];
    float4 kv = __ldg((const float4*)(Kc + (size_t)idx * D) + c4);
    float4 fv = __ldg((const float4*)(f + (size_t)row * D) + c4);
    ((float4*)(out + OFF_F))[(size_t)row * (D / 4) + c4] = kv;
    float dx = kv.x - fv.x, dy = kv.y - fv.y, dz = kv.z - fv.z, dw_ = kv.w - fv.w;
    float s = dx * dx + dy * dy + dz * dz + dw_ * dw_;
    float* dwp = g_dw + (size_t)idx * D + c4 * 4;
    atomicAdd(dwp + 0, fv.x);
    atomicAdd(dwp + 1, fv.y);
    atomicAdd(dwp + 2, fv.z);
    atomicAdd(dwp + 3, fv.w);
    if (c4 == 0) atomicAdd(&g_counts[idx], 1.0f);
    #pragma unroll
    for (int o = 16; o > 0; o >>= 1) s += __shfl_down_sync(0xffffffffu, s, o);
    __shared__ float sh[8];
    if ((threadIdx.x & 31) == 0) sh[threadIdx.x >> 5] = s;
    __syncthreads();
    if (threadIdx.x == 0) {
        float tot = 0.0f;
        #pragma unroll
        for (int w = 0; w < 8; w++) tot += sh[w];
        atomicAdd(&g_loss, (double)tot);
    }
}

// ---------------- kernel 6: new_ecs + n ----------------
__global__ void ecs_kernel(const float* __restrict__ ecs, float* __restrict__ out) {
    const int i = blockIdx.x * 256 + threadIdx.x;
    float newc = ecs[i] * 0.99f + 0.01f * g_counts[i];
    out[OFF_ECS + i] = newc;
    float s = newc;
    #pragma unroll
    for (int o = 16; o > 0; o >>= 1) s += __shfl_down_sync(0xffffffffu, s, o);
    __shared__ float sh[8];
    if ((threadIdx.x & 31) == 0) sh[threadIdx.x >> 5] = s;
    __syncthreads();
    if (threadIdx.x == 0) {
        float tot = 0.0f;
        #pragma unroll
        for (int w = 0; w < 8; w++) tot += sh[w];
        atomicAdd(&g_n, (double)tot);
    }
}

// ---------------- kernel 7: new_ema_w, new_K, loss ----------------
__global__ void final_kernel(const float* __restrict__ emaw, float* __restrict__ out) {
    const size_t i = (size_t)blockIdx.x * 256 + threadIdx.x;
    const int k = (int)(i >> 9);   // D = 512
    float neww = emaw[i] * 0.99f + 0.01f * g_dw[i];
    out[OFF_EMAW + i] = neww;
    float nn = (float)g_n;
    float newc = out[OFF_ECS + k];
    float smoothed = (newc + 1e-5f) / (nn + 4096.0f * 1e-5f) * nn;
    out[OFF_K + i] = neww / smoothed;
    if (i == 0)
        out[OFF_LOSS] = (float)(g_loss / ((double)N_ROWS * (double)D));
}

extern "C" void kernel_launch(void* const* d_in, const int* in_sizes, int n_in,
                              void* d_out, int out_size) {
    const float* f    = (const float*)d_in[0];  // [8,4096,512]
    const float* Kc   = (const float*)d_in[1];  // [4096,512]
    const float* ecs  = (const float*)d_in[2];  // [4096]
    const float* emaw = (const float*)d_in[3];  // [4096,512]
    float* out = (float*)d_out;

    cudaFuncSetAttribute(gemm_kernel, cudaFuncAttributeMaxDynamicSharedMemorySize, SMEM_DYN);

    zero_kernel<<<(KSZ * D) / 256, 256>>>();
    split_kernel<<<(N_ROWS * D) / 256, 256>>>(f, Kc);
    y2_kernel<<<KSZ, 128>>>(Kc);
    gemm_kernel<<<(N_ROWS / 256) * CODT, 256, SMEM_DYN>>>();
    argmin_kernel<<<N_ROWS / 8, 256>>>(f, Kc);
    gather_kernel<<<N_ROWS / 2, 256>>>(f, Kc, out);
    ecs_kernel<<<KSZ / 256, 256>>>(ecs, out);
    final_kernel<<<(KSZ * D) / 256, 256>>>(emaw, out);
}

// round 12
// speedup vs baseline: 2.5703x; 1.0807x over previous
#include <cuda_runtime.h>
#include <cuda_fp16.h>
#include <cstdint>

// Problem constants
constexpr int N_ROWS = 32768;          // 8*4096
constexpr int D      = 512;
constexpr int KSZ    = 4096;

// Output layout (float32), reference tuple order
constexpr size_t OFF_F    = 0;
constexpr size_t OFF_LOSS = (size_t)N_ROWS * D;
constexpr size_t OFF_K    = OFF_LOSS + 1;
constexpr size_t OFF_ECS  = OFF_K + (size_t)KSZ * D;
constexpr size_t OFF_EMAW = OFF_ECS + KSZ;

// ---------------- device scratch ----------------
__device__ __align__(16) __half g_fh[(size_t)N_ROWS * D];
__device__ __align__(16) __half g_kh[(size_t)KSZ * D];
__device__ __align__(16) __half g_scores[(size_t)N_ROWS * KSZ];   // 256MB approx scores
__device__ float               g_y2[KSZ];
__device__ int                 g_idx[N_ROWS];
__device__ float               g_counts[KSZ];
__device__ float               g_dw[(size_t)KSZ * D];
__device__ double              g_loss;
__device__ double              g_n;

// ---------------- helpers ----------------
__device__ __forceinline__ uint32_t smem_u32(const void* p) {
    uint32_t a;
    asm("{ .reg .u64 t; cvta.to.shared.u64 t, %1; cvt.u32.u64 %0, t; }" : "=r"(a) : "l"(p));
    return a;
}
__device__ __forceinline__ void cp16(uint32_t s, const void* g) {
    asm volatile("cp.async.cg.shared.global [%0], [%1], 16;" :: "r"(s), "l"(g));
}
__device__ __forceinline__ unsigned int fkey(float v) {
    unsigned int b = __float_as_uint(v);
    return (b & 0x80000000u) ? ~b : (b | 0x80000000u);
}
// m16n8k16 fp16 MMA, fp32 accumulate (baseline PTX, tensor pipe)
__device__ __forceinline__ void mma16(float* d, const uint32_t* a, const uint32_t* b) {
    asm volatile("mma.sync.aligned.m16n8k16.row.col.f32.f16.f16.f32 "
                 "{%0,%1,%2,%3}, {%4,%5,%6,%7}, {%8,%9}, {%0,%1,%2,%3};"
                 : "+f"(d[0]), "+f"(d[1]), "+f"(d[2]), "+f"(d[3])
                 : "r"(a[0]), "r"(a[1]), "r"(a[2]), "r"(a[3]), "r"(b[0]), "r"(b[1]));
}

// ---------------- kernel 0: zero scratch ----------------
__global__ void zero_kernel() {
    int i = blockIdx.x * blockDim.x + threadIdx.x;   // covers KSZ*D
    g_dw[i] = 0.0f;
    if (i < KSZ) g_counts[i] = 0.0f;
    if (i == 0) { g_loss = 0.0; g_n = 0.0; }
}

// ---------------- kernel 1: fp16 downcast ----------------
__global__ void split_kernel(const float* __restrict__ f, const float* __restrict__ Kc) {
    size_t i = (size_t)blockIdx.x * 256 + threadIdx.x;   // covers N_ROWS*D
    g_fh[i] = __float2half_rn(f[i]);
    if (i < (size_t)KSZ * D) g_kh[i] = __float2half_rn(Kc[i]);
}

// ---------------- kernel 2: code norms (fp32 exact) ----------------
__global__ void y2_kernel(const float* __restrict__ Kc) {
    int k = blockIdx.x;
    const float4* kv = (const float4*)(Kc + (size_t)k * D);
    float4 v = kv[threadIdx.x];
    float s = v.x * v.x + v.y * v.y + v.z * v.z + v.w * v.w;
    #pragma unroll
    for (int o = 16; o > 0; o >>= 1) s += __shfl_down_sync(0xffffffffu, s, o);
    __shared__ float sh[4];
    if ((threadIdx.x & 31) == 0) sh[threadIdx.x >> 5] = s;
    __syncthreads();
    if (threadIdx.x == 0) g_y2[k] = sh[0] + sh[1] + sh[2] + sh[3];
}

// ---------------- kernel 3: 1-term fp16 GEMM, write approx scores ----------------
// CTA tile 256 rows x 128 codes; 8 warps (4m x 2n) of 64x64; KBLK=64; 3 stages;
// register double-buffered fragments to overlap LDS with MMA.
constexpr int KBLK   = 64;             // halves per k-block
constexpr int NKB    = D / KBLK;       // 8
constexpr int STAGES = 3;
constexpr int CODT   = KSZ / 128;      // 32 code tiles (inner for L2 reuse)

// smem stage layout in halves (row stride 72 halves = 36 words: banks 4g+c,
// conflict-free for both cp.async stores and fragment LDS)
constexpr int AH_H = 0;                // A: 256 x 72
constexpr int BH_H = 18432;            // B: 128 x 72
constexpr int STG_H = 27648;           // halves per stage
constexpr uint32_t STG_B = STG_H * 2;  // 55296 B
constexpr uint32_t SMEM_DYN = STAGES * STG_B;  // 165888 B

__global__ void __launch_bounds__(256, 1)
gemm_kernel() {
    extern __shared__ __half smem[];
    __shared__ float sy2[128];

    const uint32_t sbase = smem_u32(smem);
    const int tid = threadIdx.x;
    const int wid = tid >> 5;
    const int lane = tid & 31;
    const int g = lane >> 2;        // groupID
    const int c = lane & 3;         // threadInGroup
    const int wm = wid >> 1;        // 0..3 -> warp rows wm*64
    const int wn = wid & 1;         // 0..1 -> warp cols wn*64
    const int wr = wm * 64;
    const int wc = wn * 64;

    const int codetile = blockIdx.x & (CODT - 1);
    const int rowtile  = blockIdx.x >> 5;
    const int row0  = rowtile * 256;
    const int code0 = codetile * 128;

    if (tid < 128) sy2[tid] = g_y2[code0 + tid];

    const __half* fa = g_fh + (size_t)row0 * D;
    const __half* kb_ = g_kh + (size_t)code0 * D;

    // stage fill: 12 cp.async(16B) per thread (A:8, B:4)
    auto fill = [&](int kb) {
        const uint32_t sb = sbase + (uint32_t)(kb % STAGES) * STG_B;
        const int koff = kb * KBLK;
        #pragma unroll
        for (int rep = 0; rep < 8; rep++) {           // A: 2048 chunks
            const int idx = tid + rep * 256;
            const int r = idx >> 3, kc = idx & 7;
            cp16(sb + (uint32_t)(r * 144 + kc * 16),
                 fa + (size_t)r * D + koff + kc * 8);
        }
        #pragma unroll
        for (int rep = 0; rep < 4; rep++) {           // B: 1024 chunks
            const int idx = tid + rep * 256;
            const int r = idx >> 3, kc = idx & 7;
            cp16(sb + BH_H * 2 + (uint32_t)(r * 144 + kc * 16),
                 kb_ + (size_t)r * D + koff + kc * 8);
        }
        asm volatile("cp.async.commit_group;" ::: "memory");
    };

    fill(0);
    fill(1);

    float acc[4][8][4];
    #pragma unroll
    for (int mt = 0; mt < 4; mt++)
        #pragma unroll
        for (int nt = 0; nt < 8; nt++)
            #pragma unroll
            for (int k = 0; k < 4; k++) acc[mt][nt][k] = 0.0f;

    for (int kb = 0; kb < NKB; kb++) {
        asm volatile("cp.async.wait_group 1;" ::: "memory");
        __syncthreads();
        // fill writes stage (kb+2)%3 == (kb-1)%3; reads of it finished before
        // the sync above.
        if (kb + 2 < NKB) fill(kb + 2);
        else asm volatile("cp.async.commit_group;" ::: "memory");

        const __half* S = smem + (size_t)(kb % STAGES) * STG_H;
        const __half* Sah = S + AH_H;
        const __half* Sbh = S + BH_H;

        // double-buffered fragment registers
        uint32_t ah[2][4][4], bh[2][8][2];

        auto loadfrag = [&](int ks, int buf) {
            const int k0 = ks * 16;
            #pragma unroll
            for (int nt = 0; nt < 8; nt++) {
                const int n = wc + nt * 8 + g;
                bh[buf][nt][0] = *(const uint32_t*)&Sbh[n * 72 + k0 + 2 * c];
                bh[buf][nt][1] = *(const uint32_t*)&Sbh[n * 72 + k0 + 2 * c + 8];
            }
            #pragma unroll
            for (int mt = 0; mt < 4; mt++) {
                const int r = wr + mt * 16 + g;
                ah[buf][mt][0] = *(const uint32_t*)&Sah[r * 72 + k0 + 2 * c];
                ah[buf][mt][1] = *(const uint32_t*)&Sah[(r + 8) * 72 + k0 + 2 * c];
                ah[buf][mt][2] = *(const uint32_t*)&Sah[r * 72 + k0 + 2 * c + 8];
                ah[buf][mt][3] = *(const uint32_t*)&Sah[(r + 8) * 72 + k0 + 2 * c + 8];
            }
        };

        loadfrag(0, 0);
        #pragma unroll
        for (int ks = 0; ks < 4; ks++) {
            const int cur = ks & 1;
            if (ks < 3) loadfrag(ks + 1, cur ^ 1);   // overlap with MMAs below
            #pragma unroll
            for (int mt = 0; mt < 4; mt++)
                #pragma unroll
                for (int nt = 0; nt < 8; nt++)
                    mma16(acc[mt][nt], ah[cur][mt], bh[cur][nt]);
        }
    }

    // epilogue: write approx scores (fp16) for this 256x128 tile
    #pragma unroll
    for (int mt = 0; mt < 4; mt++) {
        #pragma unroll
        for (int half = 0; half < 2; half++) {
            const int r = row0 + wr + mt * 16 + g + half * 8;
            __half* dst = g_scores + (size_t)r * KSZ + code0;
            #pragma unroll
            for (int nt = 0; nt < 8; nt++) {
                const int col = wc + nt * 8 + c * 2;
                float s0 = sy2[col]     - 2.0f * acc[mt][nt][half * 2 + 0];
                float s1 = sy2[col + 1] - 2.0f * acc[mt][nt][half * 2 + 1];
                *(__half2*)(dst + col) = __floats2half2_rn(s0, s1);
            }
        }
    }
}

// ---------------- kernel 4: exact argmin via candidate rescore ----------------
// One warp per row: scan 4096 fp16 scores, rescore all within MARGIN of the
// min exactly in fp32, pick packed-key min (ties -> lowest index).
constexpr float MARGIN = 6.0f;   // >> hard error bound (~0.9) of pass-1 scores

__global__ void __launch_bounds__(256, 4)
argmin_kernel(const float* __restrict__ f, const float* __restrict__ Kc) {
    const int w = threadIdx.x >> 5, lane = threadIdx.x & 31;
    const int row = blockIdx.x * 8 + w;
    const uint4* src = (const uint4*)(g_scores + (size_t)row * KSZ + lane * 128);

    // pass A: warp min of approx scores
    float m = 3.4e38f;
    #pragma unroll
    for (int it = 0; it < 16; it++) {
        uint4 v = src[it];
        const uint32_t vv[4] = {v.x, v.y, v.z, v.w};
        #pragma unroll
        for (int q = 0; q < 4; q++) {
            __half2 p = *(const __half2*)&vv[q];
            m = fminf(m, fminf(__low2float(p), __high2float(p)));
        }
    }
    #pragma unroll
    for (int o = 16; o > 0; o >>= 1)
        m = fminf(m, __shfl_xor_sync(0xffffffffu, m, o));
    const float thr = m + MARGIN;

    // pass B: enumerate candidates <= thr, exact fp32 rescore
    const float4* f4 = (const float4*)(f + (size_t)row * D);
    unsigned long long bestk = ~0ULL;
    for (int it = 0; it < 16; it++) {
        uint4 v = src[it];
        const uint32_t vv[4] = {v.x, v.y, v.z, v.w};
        int mask8 = 0;
        #pragma unroll
        for (int q = 0; q < 4; q++) {
            __half2 p = *(const __half2*)&vv[q];
            if (__low2float(p)  <= thr) mask8 |= 1 << (2 * q);
            if (__high2float(p) <= thr) mask8 |= 2 << (2 * q);
        }
        unsigned bal = __ballot_sync(0xffffffffu, mask8 != 0);
        while (bal) {
            const int s = __ffs(bal) - 1; bal &= bal - 1;
            int m8 = __shfl_sync(0xffffffffu, mask8, s);
            while (m8) {
                const int b = __ffs(m8) - 1; m8 &= m8 - 1;
                const int cand = s * 128 + it * 8 + b;
                // warp-cooperative exact fp32 dot
                const float4* k4 = (const float4*)(Kc + (size_t)cand * D);
                float ds = 0.0f;
                #pragma unroll
                for (int q = 0; q < 4; q++) {
                    float4 a = f4[q * 32 + lane];
                    float4 kk = k4[q * 32 + lane];
                    ds += a.x * kk.x + a.y * kk.y + a.z * kk.z + a.w * kk.w;
                }
                #pragma unroll
                for (int o = 16; o > 0; o >>= 1)
                    ds += __shfl_xor_sync(0xffffffffu, ds, o);
                const float sc = g_y2[cand] - 2.0f * ds;
                const unsigned long long key =
                    ((unsigned long long)fkey(sc) << 32) | (unsigned)cand;
                bestk = (key < bestk) ? key : bestk;
            }
        }
    }
    if (lane == 0) g_idx[row] = (int)(bestk & 0xFFFFFFFFULL);
}

// ---------------- kernel 5: gather + loss + EMA scatter ----------------
__global__ void gather_kernel(const float* __restrict__ f, const float* __restrict__ Kc,
                              float* __restrict__ out) {
    const int row = blockIdx.x * 2 + (threadIdx.x >> 7);
    const int c4  = threadIdx.x & 127;
    const int idx = g_idx[row];
    float4 kv = __ldg((const float4*)(Kc + (size_t)idx * D) + c4);
    float4 fv = __ldg((const float4*)(f + (size_t)row * D) + c4);
    ((float4*)(out + OFF_F))[(size_t)row * (D / 4) + c4] = kv;
    float dx = kv.x - fv.x, dy = kv.y - fv.y, dz = kv.z - fv.z, dw_ = kv.w - fv.w;
    float s = dx * dx + dy * dy + dz * dz + dw_ * dw_;
    float* dwp = g_dw + (size_t)idx * D + c4 * 4;
    atomicAdd(dwp + 0, fv.x);
    atomicAdd(dwp + 1, fv.y);
    atomicAdd(dwp + 2, fv.z);
    atomicAdd(dwp + 3, fv.w);
    if (c4 == 0) atomicAdd(&g_counts[idx], 1.0f);
    #pragma unroll
    for (int o = 16; o > 0; o >>= 1) s += __shfl_down_sync(0xffffffffu, s, o);
    __shared__ float sh[8];
    if ((threadIdx.x & 31) == 0) sh[threadIdx.x >> 5] = s;
    __syncthreads();
    if (threadIdx.x == 0) {
        float tot = 0.0f;
        #pragma unroll
        for (int w = 0; w < 8; w++) tot += sh[w];
        atomicAdd(&g_loss, (double)tot);
    }
}

// ---------------- kernel 6: new_ecs + n ----------------
__global__ void ecs_kernel(const float* __restrict__ ecs, float* __restrict__ out) {
    const int i = blockIdx.x * 256 + threadIdx.x;
    float newc = ecs[i] * 0.99f + 0.01f * g_counts[i];
    out[OFF_ECS + i] = newc;
    float s = newc;
    #pragma unroll
    for (int o = 16; o > 0; o >>= 1) s += __shfl_down_sync(0xffffffffu, s, o);
    __shared__ float sh[8];
    if ((threadIdx.x & 31) == 0) sh[threadIdx.x >> 5] = s;
    __syncthreads();
    if (threadIdx.x == 0) {
        float tot = 0.0f;
        #pragma unroll
        for (int w = 0; w < 8; w++) tot += sh[w];
        atomicAdd(&g_n, (double)tot);
    }
}

// ---------------- kernel 7: new_ema_w, new_K, loss ----------------
__global__ void final_kernel(const float* __restrict__ emaw, float* __restrict__ out) {
    const size_t i = (size_t)blockIdx.x * 256 + threadIdx.x;
    const int k = (int)(i >> 9);   // D = 512
    float neww = emaw[i] * 0.99f + 0.01f * g_dw[i];
    out[OFF_EMAW + i] = neww;
    float nn = (float)g_n;
    float newc = out[OFF_ECS + k];
    float smoothed = (newc + 1e-5f) / (nn + 4096.0f * 1e-5f) * nn;
    out[OFF_K + i] = neww / smoothed;
    if (i == 0)
        out[OFF_LOSS] = (float)(g_loss / ((double)N_ROWS * (double)D));
}

extern "C" void kernel_launch(void* const* d_in, const int* in_sizes, int n_in,
                              void* d_out, int out_size) {
    const float* f    = (const float*)d_in[0];  // [8,4096,512]
    const float* Kc   = (const float*)d_in[1];  // [4096,512]
    const float* ecs  = (const float*)d_in[2];  // [4096]
    const float* emaw = (const float*)d_in[3];  // [4096,512]
    float* out = (float*)d_out;

    cudaFuncSetAttribute(gemm_kernel, cudaFuncAttributeMaxDynamicSharedMemorySize, SMEM_DYN);

    zero_kernel<<<(KSZ * D) / 256, 256>>>();
    split_kernel<<<(N_ROWS * D) / 256, 256>>>(f, Kc);
    y2_kernel<<<KSZ, 128>>>(Kc);
    gemm_kernel<<<(N_ROWS / 256) * CODT, 256, SMEM_DYN>>>();
    argmin_kernel<<<N_ROWS / 8, 256>>>(f, Kc);
    gather_kernel<<<N_ROWS / 2, 256>>>(f, Kc, out);
    ecs_kernel<<<KSZ / 256, 256>>>(ecs, out);
    final_kernel<<<(KSZ * D) / 256, 256>>>(emaw, out);
}

// round 13
// speedup vs baseline: 2.9063x; 1.1307x over previous
#include <cuda_runtime.h>
#include <cuda_fp16.h>
#include <cstdint>

// Problem constants
constexpr int N_ROWS = 32768;          // 8*4096
constexpr int D      = 512;
constexpr int KSZ    = 4096;

// Output layout (float32), reference tuple order
constexpr size_t OFF_F    = 0;
constexpr size_t OFF_LOSS = (size_t)N_ROWS * D;
constexpr size_t OFF_K    = OFF_LOSS + 1;
constexpr size_t OFF_ECS  = OFF_K + (size_t)KSZ * D;
constexpr size_t OFF_EMAW = OFF_ECS + KSZ;

// ---------------- device scratch ----------------
__device__ __align__(16) __half g_fh[(size_t)N_ROWS * D];
__device__ __align__(16) __half g_kh[(size_t)KSZ * D];
__device__ __align__(16) __half g_scores[(size_t)N_ROWS * KSZ];   // 256MB approx scores
__device__ __align__(16) float  g_tmin[(size_t)N_ROWS * 128];     // per-row 32-col band mins
__device__ float               g_y2[KSZ];
__device__ int                 g_idx[N_ROWS];
__device__ float               g_counts[KSZ];
__device__ float               g_dw[(size_t)KSZ * D];
__device__ double              g_loss;
__device__ double              g_n;

// ---------------- helpers ----------------
__device__ __forceinline__ uint32_t smem_u32(const void* p) {
    uint32_t a;
    asm("{ .reg .u64 t; cvta.to.shared.u64 t, %1; cvt.u32.u64 %0, t; }" : "=r"(a) : "l"(p));
    return a;
}
__device__ __forceinline__ void cp16(uint32_t s, const void* g) {
    asm volatile("cp.async.cg.shared.global [%0], [%1], 16;" :: "r"(s), "l"(g));
}
__device__ __forceinline__ unsigned int fkey(float v) {
    unsigned int b = __float_as_uint(v);
    return (b & 0x80000000u) ? ~b : (b | 0x80000000u);
}
// m16n8k16 fp16 MMA, fp32 accumulate (baseline PTX, tensor pipe)
__device__ __forceinline__ void mma16(float* d, const uint32_t* a, const uint32_t* b) {
    asm volatile("mma.sync.aligned.m16n8k16.row.col.f32.f16.f16.f32 "
                 "{%0,%1,%2,%3}, {%4,%5,%6,%7}, {%8,%9}, {%0,%1,%2,%3};"
                 : "+f"(d[0]), "+f"(d[1]), "+f"(d[2]), "+f"(d[3])
                 : "r"(a[0]), "r"(a[1]), "r"(a[2]), "r"(a[3]), "r"(b[0]), "r"(b[1]));
}

// ---------------- kernel 1: fp16 downcast + scratch zero (fused) ----------------
__global__ void split_kernel(const float* __restrict__ f, const float* __restrict__ Kc) {
    size_t i = (size_t)blockIdx.x * 256 + threadIdx.x;   // covers N_ROWS*D
    g_fh[i] = __float2half_rn(f[i]);
    if (i < (size_t)KSZ * D) {
        g_kh[i] = __float2half_rn(Kc[i]);
        g_dw[i] = 0.0f;
    }
    if (i < KSZ) g_counts[i] = 0.0f;
    if (i == 0) { g_loss = 0.0; g_n = 0.0; }
}

// ---------------- kernel 2: code norms (fp32 exact) ----------------
__global__ void y2_kernel(const float* __restrict__ Kc) {
    int k = blockIdx.x;
    const float4* kv = (const float4*)(Kc + (size_t)k * D);
    float4 v = kv[threadIdx.x];
    float s = v.x * v.x + v.y * v.y + v.z * v.z + v.w * v.w;
    #pragma unroll
    for (int o = 16; o > 0; o >>= 1) s += __shfl_down_sync(0xffffffffu, s, o);
    __shared__ float sh[4];
    if ((threadIdx.x & 31) == 0) sh[threadIdx.x >> 5] = s;
    __syncthreads();
    if (threadIdx.x == 0) g_y2[k] = sh[0] + sh[1] + sh[2] + sh[3];
}

// ---------------- kernel 3: 1-term fp16 GEMM -> approx scores + band mins ----------------
// CTA tile 256 rows x 128 codes; 16 warps (4m x 4n) of 64x32; KBLK=64; 3 stages.
constexpr int KBLK   = 64;             // halves per k-block
constexpr int NKB    = D / KBLK;       // 8
constexpr int STAGES = 3;
constexpr int CODT   = KSZ / 128;      // 32 code tiles (inner for L2 reuse)

// smem stage layout in halves (row stride 72 halves = 36 words: banks 4g+c,
// conflict-free for both cp.async stores and fragment LDS)
constexpr int AH_H = 0;                // A: 256 x 72
constexpr int BH_H = 18432;            // B: 128 x 72
constexpr int STG_H = 27648;           // halves per stage
constexpr uint32_t STG_B = STG_H * 2;  // 55296 B
constexpr uint32_t SMEM_DYN = STAGES * STG_B;  // 165888 B

__global__ void __launch_bounds__(512, 1)
gemm_kernel() {
    extern __shared__ __half smem[];
    __shared__ float sy2[128];

    const uint32_t sbase = smem_u32(smem);
    const int tid = threadIdx.x;
    const int wid = tid >> 5;
    const int lane = tid & 31;
    const int g = lane >> 2;        // groupID
    const int c = lane & 3;         // threadInGroup
    const int wm = wid >> 2;        // 0..3 -> warp rows wm*64
    const int wn = wid & 3;         // 0..3 -> warp cols wn*32
    const int wr = wm * 64;
    const int wc = wn * 32;

    const int codetile = blockIdx.x & (CODT - 1);
    const int rowtile  = blockIdx.x >> 5;
    const int row0  = rowtile * 256;
    const int code0 = codetile * 128;

    if (tid < 128) sy2[tid] = g_y2[code0 + tid];

    const __half* fa = g_fh + (size_t)row0 * D;
    const __half* kb_ = g_kh + (size_t)code0 * D;

    // stage fill: 6 cp.async(16B) per thread (A:4, B:2)
    auto fill = [&](int kb) {
        const uint32_t sb = sbase + (uint32_t)(kb % STAGES) * STG_B;
        const int koff = kb * KBLK;
        #pragma unroll
        for (int rep = 0; rep < 4; rep++) {           // A: 2048 chunks
            const int idx = tid + rep * 512;
            const int r = idx >> 3, kc = idx & 7;
            cp16(sb + (uint32_t)(r * 144 + kc * 16),
                 fa + (size_t)r * D + koff + kc * 8);
        }
        #pragma unroll
        for (int rep = 0; rep < 2; rep++) {           // B: 1024 chunks
            const int idx = tid + rep * 512;
            const int r = idx >> 3, kc = idx & 7;
            cp16(sb + BH_H * 2 + (uint32_t)(r * 144 + kc * 16),
                 kb_ + (size_t)r * D + koff + kc * 8);
        }
        asm volatile("cp.async.commit_group;" ::: "memory");
    };

    fill(0);
    fill(1);

    float acc[4][4][4];
    #pragma unroll
    for (int mt = 0; mt < 4; mt++)
        #pragma unroll
        for (int nt = 0; nt < 4; nt++)
            #pragma unroll
            for (int k = 0; k < 4; k++) acc[mt][nt][k] = 0.0f;

    for (int kb = 0; kb < NKB; kb++) {
        asm volatile("cp.async.wait_group 1;" ::: "memory");
        __syncthreads();
        // fill writes stage (kb+2)%3 == (kb-1)%3; reads of it finished before
        // the sync above.
        if (kb + 2 < NKB) fill(kb + 2);
        else asm volatile("cp.async.commit_group;" ::: "memory");

        const __half* S = smem + (size_t)(kb % STAGES) * STG_H;
        const __half* Sah = S + AH_H;
        const __half* Sbh = S + BH_H;

        #pragma unroll
        for (int ks = 0; ks < 4; ks++) {
            const int k0 = ks * 16;
            uint32_t bh[4][2];
            #pragma unroll
            for (int nt = 0; nt < 4; nt++) {
                const int n = wc + nt * 8 + g;
                bh[nt][0] = *(const uint32_t*)&Sbh[n * 72 + k0 + 2 * c];
                bh[nt][1] = *(const uint32_t*)&Sbh[n * 72 + k0 + 2 * c + 8];
            }
            uint32_t ah[4][4];
            #pragma unroll
            for (int mt = 0; mt < 4; mt++) {
                const int r = wr + mt * 16 + g;
                ah[mt][0] = *(const uint32_t*)&Sah[r * 72 + k0 + 2 * c];
                ah[mt][1] = *(const uint32_t*)&Sah[(r + 8) * 72 + k0 + 2 * c];
                ah[mt][2] = *(const uint32_t*)&Sah[r * 72 + k0 + 2 * c + 8];
                ah[mt][3] = *(const uint32_t*)&Sah[(r + 8) * 72 + k0 + 2 * c + 8];
            }
            #pragma unroll
            for (int mt = 0; mt < 4; mt++)
                #pragma unroll
                for (int nt = 0; nt < 4; nt++)
                    mma16(acc[mt][nt], ah[mt], bh[nt]);
        }
    }

    // epilogue: write approx scores (fp16) + per-row band mins (fp32)
    #pragma unroll
    for (int mt = 0; mt < 4; mt++) {
        #pragma unroll
        for (int half = 0; half < 2; half++) {
            const int r = row0 + wr + mt * 16 + g + half * 8;
            __half* dst = g_scores + (size_t)r * KSZ + code0;
            float rmin = 3.4e38f;
            #pragma unroll
            for (int nt = 0; nt < 4; nt++) {
                const int col = wc + nt * 8 + c * 2;
                float s0 = sy2[col]     - 2.0f * acc[mt][nt][half * 2 + 0];
                float s1 = sy2[col + 1] - 2.0f * acc[mt][nt][half * 2 + 1];
                *(__half2*)(dst + col) = __floats2half2_rn(s0, s1);
                rmin = fminf(rmin, fminf(s0, s1));
            }
            rmin = fminf(rmin, __shfl_xor_sync(0xffffffffu, rmin, 1));
            rmin = fminf(rmin, __shfl_xor_sync(0xffffffffu, rmin, 2));
            if (c == 0)
                g_tmin[(size_t)r * 128 + codetile * 4 + wn] = rmin;
        }
    }
}

// ---------------- kernel 4: exact argmin via band filter + candidate rescore ----------------
// One warp per row: scan 128 fp32 band mins; for bands within MARGIN of the
// global min, scan their 32 fp16 scores; rescore candidates exactly in fp32.
constexpr float MARGIN = 6.0f;   // >> hard error bound (~1.5) of pass-1 scores

__global__ void __launch_bounds__(256, 4)
argmin_kernel(const float* __restrict__ f, const float* __restrict__ Kc) {
    const int w = threadIdx.x >> 5, lane = threadIdx.x & 31;
    const int row = blockIdx.x * 8 + w;

    // pass A: min over 128 band mins
    float4 bm = ((const float4*)(g_tmin + (size_t)row * 128))[lane];
    float m = fminf(fminf(bm.x, bm.y), fminf(bm.z, bm.w));
    #pragma unroll
    for (int o = 16; o > 0; o >>= 1)
        m = fminf(m, __shfl_xor_sync(0xffffffffu, m, o));
    const float thr = m + MARGIN;

    int bmask = (bm.x <= thr ? 1 : 0) | (bm.y <= thr ? 2 : 0)
              | (bm.z <= thr ? 4 : 0) | (bm.w <= thr ? 8 : 0);

    // pass B: enumerate candidates in hot bands, exact fp32 rescore
    const float4* f4 = (const float4*)(f + (size_t)row * D);
    unsigned long long bestk = ~0ULL;
    unsigned bal = __ballot_sync(0xffffffffu, bmask != 0);
    while (bal) {
        const int s = __ffs(bal) - 1; bal &= bal - 1;
        int mb = __shfl_sync(0xffffffffu, bmask, s);
        while (mb) {
            const int q = __ffs(mb) - 1; mb &= mb - 1;
            const int band = s * 4 + q;
            const float sc_h = __half2float(
                g_scores[(size_t)row * KSZ + band * 32 + lane]);
            unsigned cb = __ballot_sync(0xffffffffu, sc_h <= thr);
            while (cb) {
                const int cs = __ffs(cb) - 1; cb &= cb - 1;
                const int cand = band * 32 + cs;
                // warp-cooperative exact fp32 dot
                const float4* k4 = (const float4*)(Kc + (size_t)cand * D);
                float ds = 0.0f;
                #pragma unroll
                for (int qq = 0; qq < 4; qq++) {
                    float4 a = f4[qq * 32 + lane];
                    float4 kk = k4[qq * 32 + lane];
                    ds += a.x * kk.x + a.y * kk.y + a.z * kk.z + a.w * kk.w;
                }
                #pragma unroll
                for (int o = 16; o > 0; o >>= 1)
                    ds += __shfl_xor_sync(0xffffffffu, ds, o);
                const float sc = g_y2[cand] - 2.0f * ds;
                const unsigned long long key =
                    ((unsigned long long)fkey(sc) << 32) | (unsigned)cand;
                bestk = (key < bestk) ? key : bestk;
            }
        }
    }
    if (lane == 0) g_idx[row] = (int)(bestk & 0xFFFFFFFFULL);
}

// ---------------- kernel 5: gather + loss + EMA scatter ----------------
__global__ void gather_kernel(const float* __restrict__ f, const float* __restrict__ Kc,
                              float* __restrict__ out) {
    const int row = blockIdx.x * 2 + (threadIdx.x >> 7);
    const int c4  = threadIdx.x & 127;
    const int idx = g_idx[row];
    float4 kv = __ldg((const float4*)(Kc + (size_t)idx * D) + c4);
    float4 fv = __ldg((const float4*)(f + (size_t)row * D) + c4);
    ((float4*)(out + OFF_F))[(size_t)row * (D / 4) + c4] = kv;
    float dx = kv.x - fv.x, dy = kv.y - fv.y, dz = kv.z - fv.z, dw_ = kv.w - fv.w;
    float s = dx * dx + dy * dy + dz * dz + dw_ * dw_;
    float* dwp = g_dw + (size_t)idx * D + c4 * 4;
    atomicAdd(dwp + 0, fv.x);
    atomicAdd(dwp + 1, fv.y);
    atomicAdd(dwp + 2, fv.z);
    atomicAdd(dwp + 3, fv.w);
    if (c4 == 0) atomicAdd(&g_counts[idx], 1.0f);
    #pragma unroll
    for (int o = 16; o > 0; o >>= 1) s += __shfl_down_sync(0xffffffffu, s, o);
    __shared__ float sh[8];
    if ((threadIdx.x & 31) == 0) sh[threadIdx.x >> 5] = s;
    __syncthreads();
    if (threadIdx.x == 0) {
        float tot = 0.0f;
        #pragma unroll
        for (int w = 0; w < 8; w++) tot += sh[w];
        atomicAdd(&g_loss, (double)tot);
    }
}

// ---------------- kernel 6: new_ecs + n ----------------
__global__ void ecs_kernel(const float* __restrict__ ecs, float* __restrict__ out) {
    const int i = blockIdx.x * 256 + threadIdx.x;
    float newc = ecs[i] * 0.99f + 0.01f * g_counts[i];
    out[OFF_ECS + i] = newc;
    float s = newc;
    #pragma unroll
    for (int o = 16; o > 0; o >>= 1) s += __shfl_down_sync(0xffffffffu, s, o);
    __shared__ float sh[8];
    if ((threadIdx.x & 31) == 0) sh[threadIdx.x >> 5] = s;
    __syncthreads();
    if (threadIdx.x == 0) {
        float tot = 0.0f;
        #pragma unroll
        for (int w = 0; w < 8; w++) tot += sh[w];
        atomicAdd(&g_n, (double)tot);
    }
}

// ---------------- kernel 7: new_ema_w, new_K, loss ----------------
__global__ void final_kernel(const float* __restrict__ emaw, float* __restrict__ out) {
    const size_t i = (size_t)blockIdx.x * 256 + threadIdx.x;
    const int k = (int)(i >> 9);   // D = 512
    float neww = emaw[i] * 0.99f + 0.01f * g_dw[i];
    out[OFF_EMAW + i] = neww;
    float nn = (float)g_n;
    float newc = out[OFF_ECS + k];
    float smoothed = (newc + 1e-5f) / (nn + 4096.0f * 1e-5f) * nn;
    out[OFF_K + i] = neww / smoothed;
    if (i == 0)
        out[OFF_LOSS] = (float)(g_loss / ((double)N_ROWS * (double)D));
}

extern "C" void kernel_launch(void* const* d_in, const int* in_sizes, int n_in,
                              void* d_out, int out_size) {
    const float* f    = (const float*)d_in[0];  // [8,4096,512]
    const float* Kc   = (const float*)d_in[1];  // [4096,512]
    const float* ecs  = (const float*)d_in[2];  // [4096]
    const float* emaw = (const float*)d_in[3];  // [4096,512]
    float* out = (float*)d_out;

    cudaFuncSetAttribute(gemm_kernel, cudaFuncAttributeMaxDynamicSharedMemorySize, SMEM_DYN);

    split_kernel<<<(N_ROWS * D) / 256, 256>>>(f, Kc);
    y2_kernel<<<KSZ, 128>>>(Kc);
    gemm_kernel<<<(N_ROWS / 256) * CODT, 512, SMEM_DYN>>>();
    argmin_kernel<<<N_ROWS / 8, 256>>>(f, Kc);
    gather_kernel<<<N_ROWS / 2, 256>>>(f, Kc, out);
    ecs_kernel<<<KSZ / 256, 256>>>(ecs, out);
    final_kernel<<<(KSZ * D) / 256, 256>>>(emaw, out);
}

// round 14
// speedup vs baseline: 3.0417x; 1.0466x over previous
#include <cuda_runtime.h>
#include <cuda_fp16.h>
#include <cstdint>

// Problem constants
constexpr int N_ROWS = 32768;          // 8*4096
constexpr int D      = 512;
constexpr int KSZ    = 4096;

// Output layout (float32), reference tuple order
constexpr size_t OFF_F    = 0;
constexpr size_t OFF_LOSS = (size_t)N_ROWS * D;
constexpr size_t OFF_K    = OFF_LOSS + 1;
constexpr size_t OFF_ECS  = OFF_K + (size_t)KSZ * D;
constexpr size_t OFF_EMAW = OFF_ECS + KSZ;

// ---------------- device scratch ----------------
__device__ __align__(16) __half g_fh[(size_t)N_ROWS * D];
__device__ __align__(16) __half g_kh[(size_t)KSZ * D];
__device__ __align__(16) __half g_scores[(size_t)N_ROWS * KSZ];   // 256MB approx scores
__device__ __align__(16) float  g_tmin[(size_t)N_ROWS * 128];     // per-row 32-col band mins
__device__ float               g_y2[KSZ];
__device__ int                 g_idx[N_ROWS];
__device__ float               g_counts[KSZ];
__device__ float               g_dw[(size_t)KSZ * D];
__device__ double              g_loss;
__device__ double              g_n;

// ---------------- helpers ----------------
__device__ __forceinline__ uint32_t smem_u32(const void* p) {
    uint32_t a;
    asm("{ .reg .u64 t; cvta.to.shared.u64 t, %1; cvt.u32.u64 %0, t; }" : "=r"(a) : "l"(p));
    return a;
}
__device__ __forceinline__ void cp16(uint32_t s, const void* g) {
    asm volatile("cp.async.cg.shared.global [%0], [%1], 16;" :: "r"(s), "l"(g));
}
__device__ __forceinline__ unsigned int fkey(float v) {
    unsigned int b = __float_as_uint(v);
    return (b & 0x80000000u) ? ~b : (b | 0x80000000u);
}
// m16n8k16 fp16 MMA, fp32 accumulate (baseline PTX, tensor pipe)
__device__ __forceinline__ void mma16(float* d, const uint32_t* a, const uint32_t* b) {
    asm volatile("mma.sync.aligned.m16n8k16.row.col.f32.f16.f16.f32 "
                 "{%0,%1,%2,%3}, {%4,%5,%6,%7}, {%8,%9}, {%0,%1,%2,%3};"
                 : "+f"(d[0]), "+f"(d[1]), "+f"(d[2]), "+f"(d[3])
                 : "r"(a[0]), "r"(a[1]), "r"(a[2]), "r"(a[3]), "r"(b[0]), "r"(b[1]));
}
// mbarrier primitives (baseline PTX, sm_90-level, valid at compute_103)
#define MBAR_INIT(addr, cnt) \
    asm volatile("mbarrier.init.shared.b64 [%0], %1;" :: "r"(addr), "r"(cnt) : "memory")
#define MBAR_ARRIVE(addr) \
    asm volatile("mbarrier.arrive.release.cta.shared::cta.b64 _, [%0];" :: "r"(addr) : "memory")
#define CP_ARRIVE_NOINC(addr) \
    asm volatile("cp.async.mbarrier.arrive.noinc.shared::cta.b64 [%0];" :: "r"(addr) : "memory")
__device__ __forceinline__ void mbar_wait(uint32_t addr, uint32_t parity) {
    asm volatile("{\n\t.reg .pred P;\n\tWL_%=:\n\t"
                 "mbarrier.try_wait.parity.acquire.cta.shared::cta.b64 P, [%0], %1, 0x989680;\n\t"
                 "@P bra.uni WD_%=;\n\tbra.uni WL_%=;\n\tWD_%=:\n\t}"
                 :: "r"(addr), "r"(parity) : "memory");
}

// ---------------- kernel 1: fp16 downcast + scratch zero (fused) ----------------
__global__ void split_kernel(const float* __restrict__ f, const float* __restrict__ Kc) {
    size_t i = (size_t)blockIdx.x * 256 + threadIdx.x;   // covers N_ROWS*D
    g_fh[i] = __float2half_rn(f[i]);
    if (i < (size_t)KSZ * D) {
        g_kh[i] = __float2half_rn(Kc[i]);
        g_dw[i] = 0.0f;
    }
    if (i < KSZ) g_counts[i] = 0.0f;
    if (i == 0) { g_loss = 0.0; g_n = 0.0; }
}

// ---------------- kernel 2: code norms (fp32 exact) ----------------
__global__ void y2_kernel(const float* __restrict__ Kc) {
    int k = blockIdx.x;
    const float4* kv = (const float4*)(Kc + (size_t)k * D);
    float4 v = kv[threadIdx.x];
    float s = v.x * v.x + v.y * v.y + v.z * v.z + v.w * v.w;
    #pragma unroll
    for (int o = 16; o > 0; o >>= 1) s += __shfl_down_sync(0xffffffffu, s, o);
    __shared__ float sh[4];
    if ((threadIdx.x & 31) == 0) sh[threadIdx.x >> 5] = s;
    __syncthreads();
    if (threadIdx.x == 0) g_y2[k] = sh[0] + sh[1] + sh[2] + sh[3];
}

// ---------------- kernel 3: 1-term fp16 GEMM -> approx scores + band mins ----------------
// CTA tile 256 rows x 128 codes; 16 warps (4m x 4n) of 64x32; KBLK=64; 3 stages.
// Warp-autonomous mbarrier pipeline: no CTA-wide barriers in the mainloop,
// warps skew up to ~2 k-blocks so one warp's stalls hide under another's MMAs.
constexpr int KBLK   = 64;             // halves per k-block
constexpr int NKB    = D / KBLK;       // 8
constexpr int STAGES = 3;
constexpr int CODT   = KSZ / 128;      // 32 code tiles (inner for L2 reuse)

// smem stage layout in halves (row stride 72 halves = 36 words: banks 4g+c,
// conflict-free for both cp.async stores and fragment LDS)
constexpr int AH_H = 0;                // A: 256 x 72
constexpr int BH_H = 18432;            // B: 128 x 72
constexpr int STG_H = 27648;           // halves per stage
constexpr uint32_t STG_B = STG_H * 2;  // 55296 B
constexpr uint32_t SMEM_DYN = STAGES * STG_B;  // 165888 B

__global__ void __launch_bounds__(512, 1)
gemm_kernel() {
    extern __shared__ __half smem[];
    __shared__ float sy2[128];
    __shared__ __align__(8) unsigned long long mb_full[STAGES];
    __shared__ __align__(8) unsigned long long mb_empty[STAGES];

    const uint32_t sbase = smem_u32(smem);
    const uint32_t fullb = smem_u32(mb_full);
    const uint32_t emptyb = smem_u32(mb_empty);
    const int tid = threadIdx.x;
    const int wid = tid >> 5;
    const int lane = tid & 31;
    const int g = lane >> 2;        // groupID
    const int c = lane & 3;         // threadInGroup
    const int wm = wid >> 2;        // 0..3 -> warp rows wm*64
    const int wn = wid & 3;         // 0..3 -> warp cols wn*32
    const int wr = wm * 64;
    const int wc = wn * 32;

    const int codetile = blockIdx.x & (CODT - 1);
    const int rowtile  = blockIdx.x >> 5;
    const int row0  = rowtile * 256;
    const int code0 = codetile * 128;

    if (tid < 128) sy2[tid] = g_y2[code0 + tid];
    if (tid < STAGES) {
        MBAR_INIT(fullb + 8 * tid, 512u);   // one cp-arrive per thread
        MBAR_INIT(emptyb + 8 * tid, 16u);   // one arrive per warp
    }
    __syncthreads();   // barriers + sy2 visible; only CTA-wide sync in kernel

    const __half* fa = g_fh + (size_t)row0 * D;
    const __half* kb_ = g_kh + (size_t)code0 * D;

    // per-thread fill slice: 6 cp.async(16B) + async arrive on full[s]
    auto fill = [&](int kb) {
        const int s = kb % STAGES;
        const uint32_t sb = sbase + (uint32_t)s * STG_B;
        const int koff = kb * KBLK;
        #pragma unroll
        for (int rep = 0; rep < 4; rep++) {           // A: 2048 chunks
            const int idx = tid + rep * 512;
            const int r = idx >> 3, kc = idx & 7;
            cp16(sb + (uint32_t)(r * 144 + kc * 16),
                 fa + (size_t)r * D + koff + kc * 8);
        }
        #pragma unroll
        for (int rep = 0; rep < 2; rep++) {           // B: 1024 chunks
            const int idx = tid + rep * 512;
            const int r = idx >> 3, kc = idx & 7;
            cp16(sb + BH_H * 2 + (uint32_t)(r * 144 + kc * 16),
                 kb_ + (size_t)r * D + koff + kc * 8);
        }
        CP_ARRIVE_NOINC(fullb + 8 * s);
    };

    fill(0);
    fill(1);

    float acc[4][4][4];
    #pragma unroll
    for (int mt = 0; mt < 4; mt++)
        #pragma unroll
        for (int nt = 0; nt < 4; nt++)
            #pragma unroll
            for (int k = 0; k < 4; k++) acc[mt][nt][k] = 0.0f;

    for (int kb = 0; kb < NKB; kb++) {
        const int s = kb % STAGES;
        // prefetch stage for kb+2 (gated on its previous occupant being consumed)
        if (kb + 2 < NKB) {
            const int j = kb + 2, sj = j % STAGES;
            if (j >= STAGES)
                mbar_wait(emptyb + 8 * sj, (uint32_t)((j / STAGES - 1) & 1));
            fill(j);
        }
        // wait for this stage's data
        mbar_wait(fullb + 8 * s, (uint32_t)((kb / STAGES) & 1));

        const __half* S = smem + (size_t)s * STG_H;
        const __half* Sah = S + AH_H;
        const __half* Sbh = S + BH_H;

        #pragma unroll
        for (int ks = 0; ks < 4; ks++) {
            const int k0 = ks * 16;
            uint32_t bh[4][2];
            #pragma unroll
            for (int nt = 0; nt < 4; nt++) {
                const int n = wc + nt * 8 + g;
                bh[nt][0] = *(const uint32_t*)&Sbh[n * 72 + k0 + 2 * c];
                bh[nt][1] = *(const uint32_t*)&Sbh[n * 72 + k0 + 2 * c + 8];
            }
            uint32_t ah[4][4];
            #pragma unroll
            for (int mt = 0; mt < 4; mt++) {
                const int r = wr + mt * 16 + g;
                ah[mt][0] = *(const uint32_t*)&Sah[r * 72 + k0 + 2 * c];
                ah[mt][1] = *(const uint32_t*)&Sah[(r + 8) * 72 + k0 + 2 * c];
                ah[mt][2] = *(const uint32_t*)&Sah[r * 72 + k0 + 2 * c + 8];
                ah[mt][3] = *(const uint32_t*)&Sah[(r + 8) * 72 + k0 + 2 * c + 8];
            }
            #pragma unroll
            for (int mt = 0; mt < 4; mt++)
                #pragma unroll
                for (int nt = 0; nt < 4; nt++)
                    mma16(acc[mt][nt], ah[mt], bh[nt]);
        }
        // this warp is done reading stage s (MMAs issued in-order after LDS)
        if (lane == 0) MBAR_ARRIVE(emptyb + 8 * s);
    }

    // epilogue: write approx scores (fp16) + per-row band mins (fp32)
    #pragma unroll
    for (int mt = 0; mt < 4; mt++) {
        #pragma unroll
        for (int half = 0; half < 2; half++) {
            const int r = row0 + wr + mt * 16 + g + half * 8;
            __half* dst = g_scores + (size_t)r * KSZ + code0;
            float rmin = 3.4e38f;
            #pragma unroll
            for (int nt = 0; nt < 4; nt++) {
                const int col = wc + nt * 8 + c * 2;
                float s0 = sy2[col]     - 2.0f * acc[mt][nt][half * 2 + 0];
                float s1 = sy2[col + 1] - 2.0f * acc[mt][nt][half * 2 + 1];
                *(__half2*)(dst + col) = __floats2half2_rn(s0, s1);
                rmin = fminf(rmin, fminf(s0, s1));
            }
            rmin = fminf(rmin, __shfl_xor_sync(0xffffffffu, rmin, 1));
            rmin = fminf(rmin, __shfl_xor_sync(0xffffffffu, rmin, 2));
            if (c == 0)
                g_tmin[(size_t)r * 128 + codetile * 4 + wn] = rmin;
        }
    }
}

// ---------------- kernel 4: exact argmin via band filter + candidate rescore ----------------
constexpr float MARGIN = 6.0f;   // >> hard error bound (~1.5) of pass-1 scores

__global__ void __launch_bounds__(256, 4)
argmin_kernel(const float* __restrict__ f, const float* __restrict__ Kc) {
    const int w = threadIdx.x >> 5, lane = threadIdx.x & 31;
    const int row = blockIdx.x * 8 + w;

    // pass A: min over 128 band mins
    float4 bm = ((const float4*)(g_tmin + (size_t)row * 128))[lane];
    float m = fminf(fminf(bm.x, bm.y), fminf(bm.z, bm.w));
    #pragma unroll
    for (int o = 16; o > 0; o >>= 1)
        m = fminf(m, __shfl_xor_sync(0xffffffffu, m, o));
    const float thr = m + MARGIN;

    int bmask = (bm.x <= thr ? 1 : 0) | (bm.y <= thr ? 2 : 0)
              | (bm.z <= thr ? 4 : 0) | (bm.w <= thr ? 8 : 0);

    // pass B: enumerate candidates in hot bands, exact fp32 rescore
    const float4* f4 = (const float4*)(f + (size_t)row * D);
    unsigned long long bestk = ~0ULL;
    unsigned bal = __ballot_sync(0xffffffffu, bmask != 0);
    while (bal) {
        const int s = __ffs(bal) - 1; bal &= bal - 1;
        int mb = __shfl_sync(0xffffffffu, bmask, s);
        while (mb) {
            const int q = __ffs(mb) - 1; mb &= mb - 1;
            const int band = s * 4 + q;
            const float sc_h = __half2float(
                g_scores[(size_t)row * KSZ + band * 32 + lane]);
            unsigned cb = __ballot_sync(0xffffffffu, sc_h <= thr);
            while (cb) {
                const int cs = __ffs(cb) - 1; cb &= cb - 1;
                const int cand = band * 32 + cs;
                // warp-cooperative exact fp32 dot
                const float4* k4 = (const float4*)(Kc + (size_t)cand * D);
                float ds = 0.0f;
                #pragma unroll
                for (int qq = 0; qq < 4; qq++) {
                    float4 a = f4[qq * 32 + lane];
                    float4 kk = k4[qq * 32 + lane];
                    ds += a.x * kk.x + a.y * kk.y + a.z * kk.z + a.w * kk.w;
                }
                #pragma unroll
                for (int o = 16; o > 0; o >>= 1)
                    ds += __shfl_xor_sync(0xffffffffu, ds, o);
                const float sc = g_y2[cand] - 2.0f * ds;
                const unsigned long long key =
                    ((unsigned long long)fkey(sc) << 32) | (unsigned)cand;
                bestk = (key < bestk) ? key : bestk;
            }
        }
    }
    if (lane == 0) g_idx[row] = (int)(bestk & 0xFFFFFFFFULL);
}

// ---------------- kernel 5: gather + loss + EMA scatter ----------------
__global__ void gather_kernel(const float* __restrict__ f, const float* __restrict__ Kc,
                              float* __restrict__ out) {
    const int row = blockIdx.x * 2 + (threadIdx.x >> 7);
    const int c4  = threadIdx.x & 127;
    const int idx = g_idx[row];
    float4 kv = __ldg((const float4*)(Kc + (size_t)idx * D) + c4);
    float4 fv = __ldg((const float4*)(f + (size_t)row * D) + c4);
    ((float4*)(out + OFF_F))[(size_t)row * (D / 4) + c4] = kv;
    float dx = kv.x - fv.x, dy = kv.y - fv.y, dz = kv.z - fv.z, dw_ = kv.w - fv.w;
    float s = dx * dx + dy * dy + dz * dz + dw_ * dw_;
    float* dwp = g_dw + (size_t)idx * D + c4 * 4;
    atomicAdd(dwp + 0, fv.x);
    atomicAdd(dwp + 1, fv.y);
    atomicAdd(dwp + 2, fv.z);
    atomicAdd(dwp + 3, fv.w);
    if (c4 == 0) atomicAdd(&g_counts[idx], 1.0f);
    #pragma unroll
    for (int o = 16; o > 0; o >>= 1) s += __shfl_down_sync(0xffffffffu, s, o);
    __shared__ float sh[8];
    if ((threadIdx.x & 31) == 0) sh[threadIdx.x >> 5] = s;
    __syncthreads();
    if (threadIdx.x == 0) {
        float tot = 0.0f;
        #pragma unroll
        for (int w = 0; w < 8; w++) tot += sh[w];
        atomicAdd(&g_loss, (double)tot);
    }
}

// ---------------- kernel 6: new_ecs + n ----------------
__global__ void ecs_kernel(const float* __restrict__ ecs, float* __restrict__ out) {
    const int i = blockIdx.x * 256 + threadIdx.x;
    float newc = ecs[i] * 0.99f + 0.01f * g_counts[i];
    out[OFF_ECS + i] = newc;
    float s = newc;
    #pragma unroll
    for (int o = 16; o > 0; o >>= 1) s += __shfl_down_sync(0xffffffffu, s, o);
    __shared__ float sh[8];
    if ((threadIdx.x & 31) == 0) sh[threadIdx.x >> 5] = s;
    __syncthreads();
    if (threadIdx.x == 0) {
        float tot = 0.0f;
        #pragma unroll
        for (int w = 0; w < 8; w++) tot += sh[w];
        atomicAdd(&g_n, (double)tot);
    }
}

// ---------------- kernel 7: new_ema_w, new_K, loss ----------------
__global__ void final_kernel(const float* __restrict__ emaw, float* __restrict__ out) {
    const size_t i = (size_t)blockIdx.x * 256 + threadIdx.x;
    const int k = (int)(i >> 9);   // D = 512
    float neww = emaw[i] * 0.99f + 0.01f * g_dw[i];
    out[OFF_EMAW + i] = neww;
    float nn = (float)g_n;
    float newc = out[OFF_ECS + k];
    float smoothed = (newc + 1e-5f) / (nn + 4096.0f * 1e-5f) * nn;
    out[OFF_K + i] = neww / smoothed;
    if (i == 0)
        out[OFF_LOSS] = (float)(g_loss / ((double)N_ROWS * (double)D));
}

extern "C" void kernel_launch(void* const* d_in, const int* in_sizes, int n_in,
                              void* d_out, int out_size) {
    const float* f    = (const float*)d_in[0];  // [8,4096,512]
    const float* Kc   = (const float*)d_in[1];  // [4096,512]
    const float* ecs  = (const float*)d_in[2];  // [4096]
    const float* emaw = (const float*)d_in[3];  // [4096,512]
    float* out = (float*)d_out;

    cudaFuncSetAttribute(gemm_kernel, cudaFuncAttributeMaxDynamicSharedMemorySize, SMEM_DYN);

    split_kernel<<<(N_ROWS * D) / 256, 256>>>(f, Kc);
    y2_kernel<<<KSZ, 128>>>(Kc);
    gemm_kernel<<<(N_ROWS / 256) * CODT, 512, SMEM_DYN>>>();
    argmin_kernel<<<N_ROWS / 8, 256>>>(f, Kc);
    gather_kernel<<<N_ROWS / 2, 256>>>(f, Kc, out);
    ecs_kernel<<<KSZ / 256, 256>>>(ecs, out);
    final_kernel<<<(KSZ * D) / 256, 256>>>(emaw, out);
}